// round 4
// baseline (speedup 1.0000x reference)
#include <cuda_runtime.h>
#include <math.h>

#define N_NODES 50000
#define D 256
#define D4 1024
#define NQ 128
#define PG 256
#define E1C 32768
#define E0C 32768
#define ME 64

// ---------------- scratch (static device globals; referenced ONLY from device code) ----------------
__device__ __align__(16) float g_M[D4 * D4];   // Wq^T Wk
__device__ __align__(16) float g_v[NQ * D];
__device__ __align__(16) float g_wz[NQ * D];
__device__ __align__(16) float g_u[NQ * D];
__device__ float g_c[NQ];
__device__ __align__(16) float g_T1[N_NODES * D];
__device__ __align__(16) float g_T2[N_NODES * D];
__device__ __align__(16) float g_R1[E1C * D];
__device__ __align__(16) float g_R2[E1C * D];
__device__ float g_logits[E1C];
__device__ float g_exp[E1C];
__device__ float g_soft[E1C];
__device__ float g_target[E1C];
__device__ unsigned g_segmax[N_NODES];
__device__ float g_segsum[N_NODES];
__device__ int g_flag[N_NODES];
__device__ __align__(16) float g_NR1[N_NODES * D];
__device__ __align__(16) float g_NR2[N_NODES * D];
__device__ int g_s1[E1C], g_d1[E1C], g_q1[E1C];
__device__ int g_s0[E0C], g_d0[E0C], g_q0[E0C];
__device__ int g_psrc[NQ * ME], g_pdst[NQ * ME];
__device__ float g_psoft[NQ * ME], g_ptgt[NQ * ME];

// buffer ids for device-side resolution
#define BUF_T1 1
#define BUF_T2 2
#define BUF_R1 3
#define BUF_R2 4
#define BUF_NR1 5
#define BUF_NR2 6

__device__ __forceinline__ float* dbuf(int id) {
    switch (id) {
        case BUF_T1: return g_T1;
        case BUF_T2: return g_T2;
        case BUF_R1: return g_R1;
        case BUF_R2: return g_R2;
        case BUF_NR1: return g_NR1;
        default: return g_NR2;
    }
}

// order-preserving float<->uint for atomicMax
__device__ __forceinline__ unsigned fenc(float f) {
    unsigned u = __float_as_uint(f);
    return (u & 0x80000000u) ? ~u : (u | 0x80000000u);
}
__device__ __forceinline__ float fdec(unsigned e) {
    return __uint_as_float((e & 0x80000000u) ? (e ^ 0x80000000u) : ~e);
}

// ---------------- kernels ----------------

// g_M = Wq^T * Wk
__global__ void k_gemm_AtB(const float* __restrict__ A, const float* __restrict__ B) {
    __shared__ float As[16][68];
    __shared__ float Bs[16][68];
    int i0 = blockIdx.y * 64, j0 = blockIdx.x * 64;
    int tid = threadIdx.x;
    int tx = tid & 15, ty = tid >> 4;
    float acc[4][4];
#pragma unroll
    for (int r = 0; r < 4; r++)
#pragma unroll
        for (int c = 0; c < 4; c++) acc[r][c] = 0.f;

    for (int k0 = 0; k0 < D4; k0 += 16) {
#pragma unroll
        for (int t = tid; t < 1024; t += 256) {
            int kk = t >> 6, ii = t & 63;
            As[kk][ii] = A[(size_t)(k0 + kk) * D4 + i0 + ii];
            Bs[kk][ii] = B[(size_t)(k0 + kk) * D4 + j0 + ii];
        }
        __syncthreads();
#pragma unroll
        for (int kk = 0; kk < 16; kk++) {
            float a[4], b[4];
#pragma unroll
            for (int r = 0; r < 4; r++) a[r] = As[kk][ty * 4 + r];
#pragma unroll
            for (int c = 0; c < 4; c++) b[c] = Bs[kk][tx * 4 + c];
#pragma unroll
            for (int r = 0; r < 4; r++)
#pragma unroll
                for (int c = 0; c < 4; c++) acc[r][c] += a[r] * b[c];
        }
        __syncthreads();
    }
#pragma unroll
    for (int r = 0; r < 4; r++)
#pragma unroll
        for (int c = 0; c < 4; c++)
            g_M[(size_t)(i0 + ty * 4 + r) * D4 + j0 + tx * 4 + c] = acc[r][c];
}

// C[R x 256] = act( X[R x 256] @ W^T + bias )
__global__ void k_gemm_nt(const float* __restrict__ xext, int xid, int R,
                          const float* __restrict__ wext, long woff, int ldw,
                          const float* __restrict__ bias, int act,
                          float* __restrict__ cext, int cid) {
    const float* X = xid ? dbuf(xid) : xext;
    const float* W = (woff >= 0) ? (g_M + woff) : wext;
    float* C = cid ? dbuf(cid) : cext;

    __shared__ float Xs[16][68];
    __shared__ float Ws[16][68];
    int r0 = blockIdx.x * 64, j0 = blockIdx.y * 64;
    int tid = threadIdx.x;
    int tx = tid & 15, ty = tid >> 4;
    int rr = tid >> 2;
    int kk4 = (tid & 3) << 2;
    float acc[4][4];
#pragma unroll
    for (int r = 0; r < 4; r++)
#pragma unroll
        for (int c = 0; c < 4; c++) acc[r][c] = 0.f;

    for (int k0 = 0; k0 < D; k0 += 16) {
        float4 xv = make_float4(0.f, 0.f, 0.f, 0.f);
        if (r0 + rr < R) xv = *(const float4*)(X + (size_t)(r0 + rr) * D + k0 + kk4);
        Xs[kk4 + 0][rr] = xv.x; Xs[kk4 + 1][rr] = xv.y;
        Xs[kk4 + 2][rr] = xv.z; Xs[kk4 + 3][rr] = xv.w;
        float4 wv = *(const float4*)(W + (size_t)(j0 + rr) * ldw + k0 + kk4);
        Ws[kk4 + 0][rr] = wv.x; Ws[kk4 + 1][rr] = wv.y;
        Ws[kk4 + 2][rr] = wv.z; Ws[kk4 + 3][rr] = wv.w;
        __syncthreads();
#pragma unroll
        for (int kk = 0; kk < 16; kk++) {
            float a[4], b[4];
#pragma unroll
            for (int r = 0; r < 4; r++) a[r] = Xs[kk][ty * 4 + r];
#pragma unroll
            for (int c = 0; c < 4; c++) b[c] = Ws[kk][tx * 4 + c];
#pragma unroll
            for (int r = 0; r < 4; r++)
#pragma unroll
                for (int c = 0; c < 4; c++) acc[r][c] += a[r] * b[c];
        }
        __syncthreads();
    }
#pragma unroll
    for (int r = 0; r < 4; r++) {
        int row = r0 + ty * 4 + r;
        if (row < R) {
#pragma unroll
            for (int c = 0; c < 4; c++) {
                int col = j0 + tx * 4 + c;
                float vv = acc[r][c];
                if (bias) vv += bias[col];
                if (act) vv = vv > 0.f ? vv : 0.01f * vv;
                C[(size_t)row * D + col] = vv;
            }
        }
    }
}

// edges are int32 rows of stride s32 (8 for int32 data, 16 for int64-as-int32; field f at f*fm)
__global__ void k_extract(const int* __restrict__ e1, const int* __restrict__ e0,
                          int s32, int fm) {
    int i = blockIdx.x * blockDim.x + threadIdx.x;
    if (i < E1C) {
        int q = e1[(size_t)i * s32 + 0 * fm];
        int s = e1[(size_t)i * s32 + 6 * fm];
        int d = e1[(size_t)i * s32 + 7 * fm];
        g_q1[i] = ((unsigned)q < NQ) ? q : 0;
        g_s1[i] = ((unsigned)s < N_NODES) ? s : 0;
        g_d1[i] = ((unsigned)d < N_NODES) ? d : 0;
    }
    if (i < E0C) {
        int q = e0[(size_t)i * s32 + 0 * fm];
        int s = e0[(size_t)i * s32 + 6 * fm];
        int d = e0[(size_t)i * s32 + 7 * fm];
        g_q0[i] = ((unsigned)q < NQ) ? q : 0;
        g_s0[i] = ((unsigned)s < N_NODES) ? s : 0;
        g_d0[i] = ((unsigned)d < N_NODES) ? d : 0;
    }
}

// per-query vectors from blocks of M = Wq^T Wk
__global__ void k_queryvec(const float* __restrict__ qst, const float* __restrict__ qr) {
    int q = blockIdx.x;
    int j = threadIdx.x;
    __shared__ float ss[256], tt[256], red[256];
    ss[j] = qst[q * D + j];
    tt[j] = qr[q * D + j];
    __syncthreads();
    int which = blockIdx.y;
    if (which == 0) {
        const float* row = g_M + (size_t)j * D4;
        float a = 0.f;
        for (int k = 0; k < D; k++) a += row[512 + k] * ss[k] + row[768 + k] * tt[k];
        g_v[q * D + j] = a;
    } else if (which == 1) {
        const float* row = g_M + (size_t)(256 + j) * D4;
        float a = 0.f;
        for (int k = 0; k < D; k++) a += row[512 + k] * ss[k] + row[768 + k] * tt[k];
        for (int k = 0; k < D; k++)
            a += g_M[(size_t)(512 + k) * D4 + 256 + j] * ss[k]
               + g_M[(size_t)(768 + k) * D4 + 256 + j] * tt[k];
        g_wz[q * D + j] = a;
    } else if (which == 2) {
        float a = 0.f;
        for (int k = 0; k < D; k++)
            a += g_M[(size_t)(512 + k) * D4 + j] * ss[k]
               + g_M[(size_t)(768 + k) * D4 + j] * tt[k];
        g_u[q * D + j] = a;
    } else {
        const float* rs = g_M + (size_t)(512 + j) * D4;
        const float* rt = g_M + (size_t)(768 + j) * D4;
        float ps = 0.f, pt = 0.f;
        for (int k = 0; k < D; k++) {
            ps += rs[512 + k] * ss[k] + rs[768 + k] * tt[k];
            pt += rt[512 + k] * ss[k] + rt[768 + k] * tt[k];
        }
        red[j] = ss[j] * ps + tt[j] * pt;
        __syncthreads();
        for (int s = 128; s; s >>= 1) {
            if (j < s) red[j] += red[j + s];
            __syncthreads();
        }
        if (j == 0) g_c[q] = red[0];
    }
}

// one warp per edge
__global__ void k_edge_score(int pass, int nrid, const float* __restrict__ nrext,
                             const float* __restrict__ rel, int ne) {
    int e = blockIdx.x * 8 + (threadIdx.x >> 5);
    if (e >= ne) return;
    int lane = threadIdx.x & 31;
    const int* qs = pass ? g_q1 : g_q0;
    const int* ssrc = pass ? g_s1 : g_s0;
    const int* sdst = pass ? g_d1 : g_d0;
    const float* NR = nrid ? dbuf(nrid) : nrext;
    int q = qs[e], s = ssrc[e], d = sdst[e];
    const float* ns = NR + (size_t)s * D;
    const float* nd = NR + (size_t)d * D;
    const float* re = rel + (size_t)e * D;
    const float* t1 = g_T1 + (size_t)d * D;
    const float* t2 = g_T2 + (size_t)d * D;
    const float* r1 = g_R1 + (size_t)e * D;
    const float* r2 = g_R2 + (size_t)e * D;
    const float* vq = g_v + q * D;
    const float* wq = g_wz + q * D;
    const float* uq = g_u + q * D;
    float a = 0.f;
#pragma unroll
    for (int i = 0; i < 8; i++) {
        int k = lane + 32 * i;
        a += ns[k] * (t1[k] + r1[k] + vq[k]);
        a += re[k] * (t2[k] + r2[k] + wq[k]);
        a += uq[k] * nd[k];
    }
#pragma unroll
    for (int o = 16; o; o >>= 1) a += __shfl_xor_sync(0xffffffffu, a, o);
    if (lane == 0) g_logits[e] = a + g_c[q];
}

__global__ void k_seg_init() {
    int i = blockIdx.x * blockDim.x + threadIdx.x;
    if (i < N_NODES) {
        g_segmax[i] = 0u;
        g_segsum[i] = 0.f;
        g_flag[i] = 0;
    }
}

__global__ void k_seg_max(int pass, int ne) {
    int i = blockIdx.x * blockDim.x + threadIdx.x;
    if (i < ne) {
        const int* seg = pass ? g_s1 : g_s0;
        atomicMax(&g_segmax[seg[i]], fenc(g_logits[i]));
    }
}

__global__ void k_seg_exp(int pass, int ne) {
    int i = blockIdx.x * blockDim.x + threadIdx.x;
    if (i < ne) {
        const int* seg = pass ? g_s1 : g_s0;
        float m = fdec(g_segmax[seg[i]]);
        float e = expf(g_logits[i] - m);
        g_exp[i] = e;
        atomicAdd(&g_segsum[seg[i]], e);
    }
}

__global__ void k_seg_div(int pass, const float* __restrict__ vscore, int ne) {
    int i = blockIdx.x * blockDim.x + threadIdx.x;
    if (i < ne) {
        const int* seg = pass ? g_s1 : g_s0;
        float sft = g_exp[i] / g_segsum[seg[i]];
        g_soft[i] = sft;
        if (vscore) g_target[i] = sft * vscore[seg[i]];
    }
}

// per-query bitonic sort of 256 (target, idx), descending value, ties by ascending idx
__global__ void k_topk(const int* __restrict__ edges1, int s32, int fm,
                       float* __restrict__ out_pe, float* __restrict__ out_oi) {
    int q = blockIdx.x;
    int t = threadIdx.x;
    __shared__ float sv[256];
    __shared__ int si[256];
    sv[t] = g_target[q * PG + t];
    si[t] = t;
    __syncthreads();
    for (int k = 2; k <= 256; k <<= 1) {
        for (int j = k >> 1; j > 0; j >>= 1) {
            int ixj = t ^ j;
            if (ixj > t) {
                float va = sv[t], vb = sv[ixj];
                int ia = si[t], ib = si[ixj];
                bool before = (va > vb) || (va == vb && ia < ib);
                bool up = ((t & k) == 0);
                if (up ? !before : before) {
                    sv[t] = vb; sv[ixj] = va;
                    si[t] = ib; si[ixj] = ia;
                }
            }
            __syncthreads();
        }
    }
    if (t < ME) {
        int oi = q * PG + si[t];
        int po = q * ME + t;
        out_oi[po] = (float)oi;
#pragma unroll
        for (int f = 0; f < 8; f++)
            out_pe[(size_t)po * 8 + f] = (float)edges1[(size_t)oi * s32 + f * fm];
        int s = edges1[(size_t)oi * s32 + 6 * fm];
        int d = edges1[(size_t)oi * s32 + 7 * fm];
        g_psrc[po] = ((unsigned)s < N_NODES) ? s : 0;
        g_pdst[po] = ((unsigned)d < N_NODES) ? d : 0;
        g_psoft[po] = g_soft[oi];
        g_ptgt[po] = sv[t];
    }
}

__global__ void k_zero_score(float* __restrict__ out_score) {
    int i = blockIdx.x * blockDim.x + threadIdx.x;
    if (i < N_NODES) out_score[i] = 0.f;
}

__global__ void k_scatter_score_flag(float* __restrict__ out_score) {
    int i = blockIdx.x * blockDim.x + threadIdx.x;
    if (i < NQ * ME) {
        atomicAdd(&out_score[g_pdst[i]], g_ptgt[i]);
        g_flag[g_psrc[i]] = 1;
    }
}

__global__ void k_set_flag0() {
    int i = blockIdx.x * blockDim.x + threadIdx.x;
    if (i < E0C) g_flag[g_s0[i]] = 1;
}

// mode 0: out = g_NR1, in = external NR ; mode 1: out = g_NR2, in = g_NR1
__global__ void k_scale_repr(int mode, const float* __restrict__ nrext) {
    size_t i = (size_t)blockIdx.x * blockDim.x + threadIdx.x;
    if (i < (size_t)N_NODES * (D / 4)) {
        const float4* in = mode ? (const float4*)g_NR1 : (const float4*)nrext;
        float4* out = mode ? (float4*)g_NR2 : (float4*)g_NR1;
        int n = (int)(i >> 6);
        float sc = g_flag[n] ? 0.2f : 1.0f;
        float4 vv = in[i];
        vv.x *= sc; vv.y *= sc; vv.z *= sc; vv.w *= sc;
        out[i] = vv;
    }
}

// mode 0: pruned edges, base external NR, acc g_NR1 ; mode 1: edges0, base g_NR1, acc g_NR2
__global__ void k_edge_agg(int mode, const float* __restrict__ nrext, int ne) {
    int e = blockIdx.x * 8 + (threadIdx.x >> 5);
    if (e >= ne) return;
    int lane = threadIdx.x & 31;
    const int* src = mode ? g_s0 : g_psrc;
    const int* dst = mode ? g_d0 : g_pdst;
    const float* w = mode ? g_soft : g_psoft;
    const float* base = mode ? g_NR1 : nrext;
    float* acc = mode ? g_NR2 : g_NR1;
    float cf = 0.8f * w[e];
    const float* bd = base + (size_t)dst[e] * D;
    float* as = acc + (size_t)src[e] * D;
#pragma unroll
    for (int i = 0; i < 8; i++) atomicAdd(as + lane + 32 * i, cf * bd[lane + 32 * i]);
}

// ---------------- host: kernel launches ONLY ----------------
extern "C" void kernel_launch(void* const* d_in, const int* in_sizes, int n_in,
                              void* d_out, int out_size) {
    // classify inputs by element count (robust to metadata ordering)
    int iVS = -1, iNR = -1, iE0 = -1, iE1 = -1, iR0 = -1, iR1 = -1;
    int iQA = -1, iQB = -1, iWA = -1, iWB = -1, iWL = -1, iBL = -1;
    for (int i = 0; i < n_in; i++) {
        long sz = in_sizes[i];
        if (sz == 50000) iVS = i;
        else if (sz == 12800000) iNR = i;
        else if (sz == 262144 || sz == 524288) { if (iE0 < 0) iE0 = i; else iE1 = i; }
        else if (sz == 8388608) { if (iR0 < 0) iR0 = i; else iR1 = i; }
        else if (sz == 32768) { if (iQA < 0) iQA = i; else iQB = i; }
        else if (sz == 1048576) { if (iWA < 0) iWA = i; else iWB = i; }
        else if (sz == 65536) iWL = i;
        else if (sz == 256) iBL = i;
    }
    // scheme detection: dict/insertion order starts with visited_node_score (50000).
    // alphabetical order puts query_rel_emb before query_src_ts_emb and Wk before Wq.
    bool dictOrder = (in_sizes[0] == 50000);

    const float* vscore = (const float*)d_in[iVS];
    const float* NR = (const float*)d_in[iNR];
    const int* e0 = (const int*)d_in[iE0];
    const int* e1 = (const int*)d_in[iE1];
    const float* rel0 = (const float*)d_in[iR0];
    const float* rel1 = (const float*)d_in[iR1];
    const float* qst = (const float*)d_in[dictOrder ? iQA : iQB];
    const float* qr = (const float*)d_in[dictOrder ? iQB : iQA];
    const float* Wq = (const float*)d_in[dictOrder ? iWA : iWB];
    const float* Wk = (const float*)d_in[dictOrder ? iWB : iWA];
    const float* Wl = (const float*)d_in[iWL];
    const float* bl = (const float*)d_in[iBL];

    // edge row stride in int32 units: 8 if int32 data, 16 if int64 (read low words)
    int s32 = in_sizes[iE0] / 32768;
    int fm = s32 >> 3;

    float* out = (float*)d_out;
    float* out_score = out;
    float* out_repr = out + N_NODES;
    float* out_pe = out_repr + (size_t)N_NODES * D;
    float* out_oi = out_pe + (size_t)NQ * ME * 8;

    const long OFF_NN = 0;
    const long OFF_RN = (long)256 * D4;
    const long OFF_NR_ = 256;
    const long OFF_RR = (long)256 * D4 + 256;

    const int NB50K = (N_NODES + 255) / 256;

    k_extract<<<128, 256>>>(e1, e0, s32, fm);
    k_gemm_AtB<<<dim3(16, 16), 256>>>(Wq, Wk);
    k_queryvec<<<dim3(NQ, 4), 256>>>(qst, qr);

    // ---- pass 1 tables ----
    k_gemm_nt<<<dim3(782, 4), 256>>>(NR, 0, N_NODES, nullptr, OFF_NN, D4, nullptr, 0, nullptr, BUF_T1);
    k_gemm_nt<<<dim3(782, 4), 256>>>(NR, 0, N_NODES, nullptr, OFF_RN, D4, nullptr, 0, nullptr, BUF_T2);
    k_gemm_nt<<<dim3(512, 4), 256>>>(rel1, 0, E1C, nullptr, OFF_NR_, D4, nullptr, 0, nullptr, BUF_R1);
    k_gemm_nt<<<dim3(512, 4), 256>>>(rel1, 0, E1C, nullptr, OFF_RR, D4, nullptr, 0, nullptr, BUF_R2);

    // ---- pass 1 scores + segment softmax ----
    k_seg_init<<<NB50K, 256>>>();
    k_edge_score<<<E1C / 8, 256>>>(1, 0, NR, rel1, E1C);
    k_seg_max<<<128, 256>>>(1, E1C);
    k_seg_exp<<<128, 256>>>(1, E1C);
    k_seg_div<<<128, 256>>>(1, vscore, E1C);

    // ---- top-64 per query ----
    k_topk<<<NQ, 256>>>(e1, s32, fm, out_pe, out_oi);

    // ---- updated node score + repr update 1 ----
    k_zero_score<<<NB50K, 256>>>(out_score);
    k_scatter_score_flag<<<(NQ * ME + 255) / 256, 256>>>(out_score);
    k_scale_repr<<<(N_NODES * (D / 4) + 255) / 256, 256>>>(0, NR);
    k_edge_agg<<<NQ * ME / 8, 256>>>(0, NR, NQ * ME);

    // ---- pass 2 tables ----
    k_gemm_nt<<<dim3(782, 4), 256>>>(nullptr, BUF_NR1, N_NODES, nullptr, OFF_NN, D4, nullptr, 0, nullptr, BUF_T1);
    k_gemm_nt<<<dim3(782, 4), 256>>>(nullptr, BUF_NR1, N_NODES, nullptr, OFF_RN, D4, nullptr, 0, nullptr, BUF_T2);
    k_gemm_nt<<<dim3(512, 4), 256>>>(rel0, 0, E0C, nullptr, OFF_NR_, D4, nullptr, 0, nullptr, BUF_R1);
    k_gemm_nt<<<dim3(512, 4), 256>>>(rel0, 0, E0C, nullptr, OFF_RR, D4, nullptr, 0, nullptr, BUF_R2);

    // ---- pass 2 scores + softmax ----
    k_seg_init<<<NB50K, 256>>>();
    k_edge_score<<<E0C / 8, 256>>>(0, BUF_NR1, nullptr, rel0, E0C);
    k_seg_max<<<128, 256>>>(0, E0C);
    k_seg_exp<<<128, 256>>>(0, E0C);
    k_seg_div<<<128, 256>>>(0, nullptr, E0C);

    // ---- repr update 2 ----
    k_set_flag0<<<128, 256>>>();
    k_scale_repr<<<(N_NODES * (D / 4) + 255) / 256, 256>>>(1, nullptr);
    k_edge_agg<<<E0C / 8, 256>>>(1, nullptr, E0C);

    // ---- final linear layer + leaky relu ----
    k_gemm_nt<<<dim3(782, 4), 256>>>(nullptr, BUF_NR2, N_NODES, Wl, -1, D, bl, 1, out_repr, 0);
}

// round 6
// speedup vs baseline: 1.0332x; 1.0332x over previous
#include <cuda_runtime.h>
#include <math.h>

#define N_NODES 50000
#define D 256
#define D4 1024
#define NQ 128
#define PG 256
#define E1C 32768
#define E0C 32768
#define ME 64
#define SPAD 132

// ---------------- scratch (static device globals; referenced ONLY from device code) ----------------
__device__ __align__(16) float g_M[D4 * D4];   // Wq^T Wk
__device__ __align__(16) float g_v[NQ * D];
__device__ __align__(16) float g_wz[NQ * D];
__device__ __align__(16) float g_u[NQ * D];
__device__ float g_c[NQ];
__device__ __align__(16) float g_T1[N_NODES * D];
__device__ __align__(16) float g_T2[N_NODES * D];
__device__ __align__(16) float g_R1[E1C * D];
__device__ __align__(16) float g_R2[E1C * D];
__device__ float g_logits[E1C];
__device__ float g_exp[E1C];
__device__ float g_soft[E1C];
__device__ float g_target[E1C];
__device__ unsigned g_segmax[N_NODES];
__device__ float g_segsum[N_NODES];
__device__ int g_flag[N_NODES];
__device__ __align__(16) float g_NR1[N_NODES * D];
__device__ __align__(16) float g_NR2[N_NODES * D];
__device__ int g_s1[E1C], g_d1[E1C], g_q1[E1C];
__device__ int g_s0[E0C], g_d0[E0C], g_q0[E0C];
__device__ int g_psrc[NQ * ME], g_pdst[NQ * ME];
__device__ float g_psoft[NQ * ME], g_ptgt[NQ * ME];

#define BUF_T1 1
#define BUF_T2 2
#define BUF_R1 3
#define BUF_R2 4
#define BUF_NR1 5
#define BUF_NR2 6

__device__ __forceinline__ float* dbuf(int id) {
    switch (id) {
        case BUF_T1: return g_T1;
        case BUF_T2: return g_T2;
        case BUF_R1: return g_R1;
        case BUF_R2: return g_R2;
        case BUF_NR1: return g_NR1;
        default: return g_NR2;
    }
}

__device__ __forceinline__ unsigned fenc(float f) {
    unsigned u = __float_as_uint(f);
    return (u & 0x80000000u) ? ~u : (u | 0x80000000u);
}
__device__ __forceinline__ float fdec(unsigned e) {
    return __uint_as_float((e & 0x80000000u) ? (e ^ 0x80000000u) : ~e);
}

// ---------------- big-tile fp32 GEMM: C[R x N] = act( X[R x 256] @ W[N x 256]^T + bias )
// 128x128 block tile, 8x8 per thread, 256 threads, double-buffered smem.
// Output columns [0,256) -> c1, [256,512) -> c2 (each ldc=256). If c1id==0 && c2id==0,
// single external output c1ext (N<=256).
__global__ __launch_bounds__(256) void k_gemm128(
    const float* __restrict__ xext, int xid, int R,
    const float* __restrict__ wext, long woff, int ldwext,
    const float* __restrict__ bias, int act,
    float* __restrict__ c1ext, int c1id, int c2id)
{
    const float* X = xid ? dbuf(xid) : xext;
    const float* W = (woff >= 0) ? (g_M + woff) : wext;
    const int ldw = (woff >= 0) ? D4 : ldwext;

    __shared__ float Xs[2][16][SPAD];
    __shared__ float Ws[2][16][SPAD];

    const int r0 = blockIdx.x * 128;
    const int j0 = blockIdx.y * 128;
    float* Cbase;
    if (c1id == 0 && c2id == 0) Cbase = c1ext + j0;
    else Cbase = (j0 < 256) ? (dbuf(c1id) + j0) : (dbuf(c2id) + (j0 - 256));

    const int tid = threadIdx.x;
    const int tx = tid & 15, ty = tid >> 4;

    float acc[8][8];
#pragma unroll
    for (int r = 0; r < 8; r++)
#pragma unroll
        for (int c = 0; c < 8; c++) acc[r][c] = 0.f;

    // G2S staging registers
    float4 xs[2], ws[2];

    // prime tile 0
#pragma unroll
    for (int i = 0; i < 2; i++) {
        int f = tid + i * 256;
        int row = f >> 2, kq = (f & 3) << 2;
        float4 v = make_float4(0.f, 0.f, 0.f, 0.f);
        if (r0 + row < R) v = *(const float4*)(X + (size_t)(r0 + row) * D + kq);
        Xs[0][kq + 0][row] = v.x; Xs[0][kq + 1][row] = v.y;
        Xs[0][kq + 2][row] = v.z; Xs[0][kq + 3][row] = v.w;
        float4 wv = *(const float4*)(W + (size_t)(j0 + row) * ldw + kq);
        Ws[0][kq + 0][row] = wv.x; Ws[0][kq + 1][row] = wv.y;
        Ws[0][kq + 2][row] = wv.z; Ws[0][kq + 3][row] = wv.w;
    }
    __syncthreads();

    for (int kb = 0; kb < 16; kb++) {
        int cur = kb & 1, nxt = cur ^ 1;
        // prefetch next tile into registers
        if (kb < 15) {
            int k0 = (kb + 1) * 16;
#pragma unroll
            for (int i = 0; i < 2; i++) {
                int f = tid + i * 256;
                int row = f >> 2, kq = (f & 3) << 2;
                xs[i] = make_float4(0.f, 0.f, 0.f, 0.f);
                if (r0 + row < R) xs[i] = *(const float4*)(X + (size_t)(r0 + row) * D + k0 + kq);
                ws[i] = *(const float4*)(W + (size_t)(j0 + row) * ldw + k0 + kq);
            }
        }
        // compute current tile
#pragma unroll
        for (int kk = 0; kk < 16; kk++) {
            float a[8], b[8];
            *(float4*)&a[0] = *(const float4*)&Xs[cur][kk][ty * 8];
            *(float4*)&a[4] = *(const float4*)&Xs[cur][kk][ty * 8 + 4];
            *(float4*)&b[0] = *(const float4*)&Ws[cur][kk][tx * 8];
            *(float4*)&b[4] = *(const float4*)&Ws[cur][kk][tx * 8 + 4];
#pragma unroll
            for (int r = 0; r < 8; r++)
#pragma unroll
                for (int c = 0; c < 8; c++) acc[r][c] += a[r] * b[c];
        }
        // commit prefetched tile
        if (kb < 15) {
#pragma unroll
            for (int i = 0; i < 2; i++) {
                int f = tid + i * 256;
                int row = f >> 2, kq = (f & 3) << 2;
                Xs[nxt][kq + 0][row] = xs[i].x; Xs[nxt][kq + 1][row] = xs[i].y;
                Xs[nxt][kq + 2][row] = xs[i].z; Xs[nxt][kq + 3][row] = xs[i].w;
                Ws[nxt][kq + 0][row] = ws[i].x; Ws[nxt][kq + 1][row] = ws[i].y;
                Ws[nxt][kq + 2][row] = ws[i].z; Ws[nxt][kq + 3][row] = ws[i].w;
            }
            __syncthreads();
        }
    }

#pragma unroll
    for (int r = 0; r < 8; r++) {
        int row = r0 + ty * 8 + r;
        if (row < R) {
            float vals[8];
#pragma unroll
            for (int c = 0; c < 8; c++) {
                float vv = acc[r][c];
                if (bias) vv += bias[j0 + tx * 8 + c];
                if (act) vv = vv > 0.f ? vv : 0.01f * vv;
                vals[c] = vv;
            }
            float* crow = Cbase + (size_t)row * D + tx * 8;
            *(float4*)crow = *(float4*)&vals[0];
            *(float4*)(crow + 4) = *(float4*)&vals[4];
        }
    }
}

// g_M = A^T * B (A, B 1024x1024 row-major), same tiling, TN loads (no transpose needed)
__global__ __launch_bounds__(256) void k_gemm128_tn(const float* __restrict__ A,
                                                    const float* __restrict__ B) {
    __shared__ float As[2][16][SPAD];
    __shared__ float Bs[2][16][SPAD];

    const int i0 = blockIdx.x * 128;
    const int j0 = blockIdx.y * 128;
    const int tid = threadIdx.x;
    const int tx = tid & 15, ty = tid >> 4;

    float acc[8][8];
#pragma unroll
    for (int r = 0; r < 8; r++)
#pragma unroll
        for (int c = 0; c < 8; c++) acc[r][c] = 0.f;

    float4 xs[2], ws[2];

#pragma unroll
    for (int i = 0; i < 2; i++) {
        int f = tid + i * 256;
        int i4 = (f & 31) << 2, kk = f >> 5;
        *(float4*)&As[0][kk][i4] = *(const float4*)(A + (size_t)kk * D4 + i0 + i4);
        *(float4*)&Bs[0][kk][i4] = *(const float4*)(B + (size_t)kk * D4 + j0 + i4);
    }
    __syncthreads();

    for (int kb = 0; kb < 64; kb++) {
        int cur = kb & 1, nxt = cur ^ 1;
        if (kb < 63) {
            int k0 = (kb + 1) * 16;
#pragma unroll
            for (int i = 0; i < 2; i++) {
                int f = tid + i * 256;
                int i4 = (f & 31) << 2, kk = f >> 5;
                xs[i] = *(const float4*)(A + (size_t)(k0 + kk) * D4 + i0 + i4);
                ws[i] = *(const float4*)(B + (size_t)(k0 + kk) * D4 + j0 + i4);
            }
        }
#pragma unroll
        for (int kk = 0; kk < 16; kk++) {
            float a[8], b[8];
            *(float4*)&a[0] = *(const float4*)&As[cur][kk][ty * 8];
            *(float4*)&a[4] = *(const float4*)&As[cur][kk][ty * 8 + 4];
            *(float4*)&b[0] = *(const float4*)&Bs[cur][kk][tx * 8];
            *(float4*)&b[4] = *(const float4*)&Bs[cur][kk][tx * 8 + 4];
#pragma unroll
            for (int r = 0; r < 8; r++)
#pragma unroll
                for (int c = 0; c < 8; c++) acc[r][c] += a[r] * b[c];
        }
        if (kb < 63) {
#pragma unroll
            for (int i = 0; i < 2; i++) {
                int f = tid + i * 256;
                int i4 = (f & 31) << 2, kk = f >> 5;
                *(float4*)&As[nxt][kk][i4] = xs[i];
                *(float4*)&Bs[nxt][kk][i4] = ws[i];
            }
            __syncthreads();
        }
    }

#pragma unroll
    for (int r = 0; r < 8; r++) {
        float* crow = g_M + (size_t)(i0 + ty * 8 + r) * D4 + j0 + tx * 8;
        *(float4*)crow = *(float4*)&acc[r][0];
        *(float4*)(crow + 4) = *(float4*)&acc[r][4];
    }
}

// edges are int32 rows of stride s32 (8 for int32 data, 16 for int64-as-int32; field f at f*fm)
__global__ void k_extract(const int* __restrict__ e1, const int* __restrict__ e0,
                          int s32, int fm) {
    int i = blockIdx.x * blockDim.x + threadIdx.x;
    if (i < E1C) {
        int q = e1[(size_t)i * s32 + 0 * fm];
        int s = e1[(size_t)i * s32 + 6 * fm];
        int d = e1[(size_t)i * s32 + 7 * fm];
        g_q1[i] = ((unsigned)q < NQ) ? q : 0;
        g_s1[i] = ((unsigned)s < N_NODES) ? s : 0;
        g_d1[i] = ((unsigned)d < N_NODES) ? d : 0;
    }
    if (i < E0C) {
        int q = e0[(size_t)i * s32 + 0 * fm];
        int s = e0[(size_t)i * s32 + 6 * fm];
        int d = e0[(size_t)i * s32 + 7 * fm];
        g_q0[i] = ((unsigned)q < NQ) ? q : 0;
        g_s0[i] = ((unsigned)s < N_NODES) ? s : 0;
        g_d0[i] = ((unsigned)d < N_NODES) ? d : 0;
    }
}

// per-query vectors from blocks of M = Wq^T Wk
__global__ void k_queryvec(const float* __restrict__ qst, const float* __restrict__ qr) {
    int q = blockIdx.x;
    int j = threadIdx.x;
    __shared__ float ss[256], tt[256], red[256];
    ss[j] = qst[q * D + j];
    tt[j] = qr[q * D + j];
    __syncthreads();
    int which = blockIdx.y;
    if (which == 0) {
        const float* row = g_M + (size_t)j * D4;
        float a = 0.f;
        for (int k = 0; k < D; k++) a += row[512 + k] * ss[k] + row[768 + k] * tt[k];
        g_v[q * D + j] = a;
    } else if (which == 1) {
        const float* row = g_M + (size_t)(256 + j) * D4;
        float a = 0.f;
        for (int k = 0; k < D; k++) a += row[512 + k] * ss[k] + row[768 + k] * tt[k];
        for (int k = 0; k < D; k++)
            a += g_M[(size_t)(512 + k) * D4 + 256 + j] * ss[k]
               + g_M[(size_t)(768 + k) * D4 + 256 + j] * tt[k];
        g_wz[q * D + j] = a;
    } else if (which == 2) {
        float a = 0.f;
        for (int k = 0; k < D; k++)
            a += g_M[(size_t)(512 + k) * D4 + j] * ss[k]
               + g_M[(size_t)(768 + k) * D4 + j] * tt[k];
        g_u[q * D + j] = a;
    } else {
        const float* rs = g_M + (size_t)(512 + j) * D4;
        const float* rt = g_M + (size_t)(768 + j) * D4;
        float ps = 0.f, pt = 0.f;
        for (int k = 0; k < D; k++) {
            ps += rs[512 + k] * ss[k] + rs[768 + k] * tt[k];
            pt += rt[512 + k] * ss[k] + rt[768 + k] * tt[k];
        }
        red[j] = ss[j] * ps + tt[j] * pt;
        __syncthreads();
        for (int s = 128; s; s >>= 1) {
            if (j < s) red[j] += red[j + s];
            __syncthreads();
        }
        if (j == 0) g_c[q] = red[0];
    }
}

// one warp per edge
__global__ void k_edge_score(int pass, int nrid, const float* __restrict__ nrext,
                             const float* __restrict__ rel, int ne) {
    int e = blockIdx.x * 8 + (threadIdx.x >> 5);
    if (e >= ne) return;
    int lane = threadIdx.x & 31;
    const int* qs = pass ? g_q1 : g_q0;
    const int* ssrc = pass ? g_s1 : g_s0;
    const int* sdst = pass ? g_d1 : g_d0;
    const float* NR = nrid ? dbuf(nrid) : nrext;
    int q = qs[e], s = ssrc[e], d = sdst[e];
    const float* ns = NR + (size_t)s * D;
    const float* nd = NR + (size_t)d * D;
    const float* re = rel + (size_t)e * D;
    const float* t1 = g_T1 + (size_t)d * D;
    const float* t2 = g_T2 + (size_t)d * D;
    const float* r1 = g_R1 + (size_t)e * D;
    const float* r2 = g_R2 + (size_t)e * D;
    const float* vq = g_v + q * D;
    const float* wq = g_wz + q * D;
    const float* uq = g_u + q * D;
    float a = 0.f;
#pragma unroll
    for (int i = 0; i < 8; i++) {
        int k = lane + 32 * i;
        a += ns[k] * (t1[k] + r1[k] + vq[k]);
        a += re[k] * (t2[k] + r2[k] + wq[k]);
        a += uq[k] * nd[k];
    }
#pragma unroll
    for (int o = 16; o; o >>= 1) a += __shfl_xor_sync(0xffffffffu, a, o);
    if (lane == 0) g_logits[e] = a + g_c[q];
}

__global__ void k_seg_init() {
    int i = blockIdx.x * blockDim.x + threadIdx.x;
    if (i < N_NODES) {
        g_segmax[i] = 0u;
        g_segsum[i] = 0.f;
        g_flag[i] = 0;
    }
}

__global__ void k_seg_max(int pass, int ne) {
    int i = blockIdx.x * blockDim.x + threadIdx.x;
    if (i < ne) {
        const int* seg = pass ? g_s1 : g_s0;
        atomicMax(&g_segmax[seg[i]], fenc(g_logits[i]));
    }
}

__global__ void k_seg_exp(int pass, int ne) {
    int i = blockIdx.x * blockDim.x + threadIdx.x;
    if (i < ne) {
        const int* seg = pass ? g_s1 : g_s0;
        float m = fdec(g_segmax[seg[i]]);
        float e = expf(g_logits[i] - m);
        g_exp[i] = e;
        atomicAdd(&g_segsum[seg[i]], e);
    }
}

__global__ void k_seg_div(int pass, const float* __restrict__ vscore, int ne) {
    int i = blockIdx.x * blockDim.x + threadIdx.x;
    if (i < ne) {
        const int* seg = pass ? g_s1 : g_s0;
        float sft = g_exp[i] / g_segsum[seg[i]];
        g_soft[i] = sft;
        if (vscore) g_target[i] = sft * vscore[seg[i]];
    }
}

// per-query bitonic sort of 256 (target, idx), descending value, ties by ascending idx
__global__ void k_topk(const int* __restrict__ edges1, int s32, int fm,
                       float* __restrict__ out_pe, float* __restrict__ out_oi) {
    int q = blockIdx.x;
    int t = threadIdx.x;
    __shared__ float sv[256];
    __shared__ int si[256];
    sv[t] = g_target[q * PG + t];
    si[t] = t;
    __syncthreads();
    for (int k = 2; k <= 256; k <<= 1) {
        for (int j = k >> 1; j > 0; j >>= 1) {
            int ixj = t ^ j;
            if (ixj > t) {
                float va = sv[t], vb = sv[ixj];
                int ia = si[t], ib = si[ixj];
                bool before = (va > vb) || (va == vb && ia < ib);
                bool up = ((t & k) == 0);
                if (up ? !before : before) {
                    sv[t] = vb; sv[ixj] = va;
                    si[t] = ib; si[ixj] = ia;
                }
            }
            __syncthreads();
        }
    }
    if (t < ME) {
        int oi = q * PG + si[t];
        int po = q * ME + t;
        out_oi[po] = (float)oi;
#pragma unroll
        for (int f = 0; f < 8; f++)
            out_pe[(size_t)po * 8 + f] = (float)edges1[(size_t)oi * s32 + f * fm];
        int s = edges1[(size_t)oi * s32 + 6 * fm];
        int d = edges1[(size_t)oi * s32 + 7 * fm];
        g_psrc[po] = ((unsigned)s < N_NODES) ? s : 0;
        g_pdst[po] = ((unsigned)d < N_NODES) ? d : 0;
        g_psoft[po] = g_soft[oi];
        g_ptgt[po] = sv[t];
    }
}

__global__ void k_zero_score(float* __restrict__ out_score) {
    int i = blockIdx.x * blockDim.x + threadIdx.x;
    if (i < N_NODES) out_score[i] = 0.f;
}

__global__ void k_scatter_score_flag(float* __restrict__ out_score) {
    int i = blockIdx.x * blockDim.x + threadIdx.x;
    if (i < NQ * ME) {
        atomicAdd(&out_score[g_pdst[i]], g_ptgt[i]);
        g_flag[g_psrc[i]] = 1;
    }
}

__global__ void k_set_flag0() {
    int i = blockIdx.x * blockDim.x + threadIdx.x;
    if (i < E0C) g_flag[g_s0[i]] = 1;
}

// mode 0: out = g_NR1, in = external NR ; mode 1: out = g_NR2, in = g_NR1
__global__ void k_scale_repr(int mode, const float* __restrict__ nrext) {
    size_t i = (size_t)blockIdx.x * blockDim.x + threadIdx.x;
    if (i < (size_t)N_NODES * (D / 4)) {
        const float4* in = mode ? (const float4*)g_NR1 : (const float4*)nrext;
        float4* out = mode ? (float4*)g_NR2 : (float4*)g_NR1;
        int n = (int)(i >> 6);
        float sc = g_flag[n] ? 0.2f : 1.0f;
        float4 vv = in[i];
        vv.x *= sc; vv.y *= sc; vv.z *= sc; vv.w *= sc;
        out[i] = vv;
    }
}

// mode 0: pruned edges, base external NR, acc g_NR1 ; mode 1: edges0, base g_NR1, acc g_NR2
__global__ void k_edge_agg(int mode, const float* __restrict__ nrext, int ne) {
    int e = blockIdx.x * 8 + (threadIdx.x >> 5);
    if (e >= ne) return;
    int lane = threadIdx.x & 31;
    const int* src = mode ? g_s0 : g_psrc;
    const int* dst = mode ? g_d0 : g_pdst;
    const float* w = mode ? g_soft : g_psoft;
    const float* base = mode ? g_NR1 : nrext;
    float* acc = mode ? g_NR2 : g_NR1;
    float cf = 0.8f * w[e];
    const float* bd = base + (size_t)dst[e] * D;
    float* as = acc + (size_t)src[e] * D;
#pragma unroll
    for (int i = 0; i < 8; i++) atomicAdd(as + lane + 32 * i, cf * bd[lane + 32 * i]);
}

// ---------------- host: kernel launches ONLY ----------------
extern "C" void kernel_launch(void* const* d_in, const int* in_sizes, int n_in,
                              void* d_out, int out_size) {
    int iVS = -1, iNR = -1, iE0 = -1, iE1 = -1, iR0 = -1, iR1 = -1;
    int iQA = -1, iQB = -1, iWA = -1, iWB = -1, iWL = -1, iBL = -1;
    for (int i = 0; i < n_in; i++) {
        long sz = in_sizes[i];
        if (sz == 50000) iVS = i;
        else if (sz == 12800000) iNR = i;
        else if (sz == 262144 || sz == 524288) { if (iE0 < 0) iE0 = i; else iE1 = i; }
        else if (sz == 8388608) { if (iR0 < 0) iR0 = i; else iR1 = i; }
        else if (sz == 32768) { if (iQA < 0) iQA = i; else iQB = i; }
        else if (sz == 1048576) { if (iWA < 0) iWA = i; else iWB = i; }
        else if (sz == 65536) iWL = i;
        else if (sz == 256) iBL = i;
    }
    bool dictOrder = (in_sizes[0] == 50000);

    const float* vscore = (const float*)d_in[iVS];
    const float* NR = (const float*)d_in[iNR];
    const int* e0 = (const int*)d_in[iE0];
    const int* e1 = (const int*)d_in[iE1];
    const float* rel0 = (const float*)d_in[iR0];
    const float* rel1 = (const float*)d_in[iR1];
    const float* qst = (const float*)d_in[dictOrder ? iQA : iQB];
    const float* qr = (const float*)d_in[dictOrder ? iQB : iQA];
    const float* Wq = (const float*)d_in[dictOrder ? iWA : iWB];
    const float* Wk = (const float*)d_in[dictOrder ? iWB : iWA];
    const float* Wl = (const float*)d_in[iWL];
    const float* bl = (const float*)d_in[iBL];

    int s32 = in_sizes[iE0] / 32768;
    int fm = s32 >> 3;

    float* out = (float*)d_out;
    float* out_score = out;
    float* out_repr = out + N_NODES;
    float* out_pe = out_repr + (size_t)N_NODES * D;
    float* out_oi = out_pe + (size_t)NQ * ME * 8;

    const int NB50K = (N_NODES + 255) / 256;
    const int GRN = (N_NODES + 127) / 128;   // 391
    const int GRE = E1C / 128;               // 256

    k_extract<<<128, 256>>>(e1, e0, s32, fm);
    k_gemm128_tn<<<dim3(8, 8), 256>>>(Wq, Wk);
    k_queryvec<<<dim3(NQ, 4), 256>>>(qst, qr);

    // ---- pass 1 tables: T1||T2 and R1||R2 fused (N=512 each) ----
    k_gemm128<<<dim3(GRN, 4), 256>>>(NR, 0, N_NODES, nullptr, 0, 0, nullptr, 0, nullptr, BUF_T1, BUF_T2);
    k_gemm128<<<dim3(GRE, 4), 256>>>(rel1, 0, E1C, nullptr, 256, 0, nullptr, 0, nullptr, BUF_R1, BUF_R2);

    // ---- pass 1 scores + segment softmax ----
    k_seg_init<<<NB50K, 256>>>();
    k_edge_score<<<E1C / 8, 256>>>(1, 0, NR, rel1, E1C);
    k_seg_max<<<128, 256>>>(1, E1C);
    k_seg_exp<<<128, 256>>>(1, E1C);
    k_seg_div<<<128, 256>>>(1, vscore, E1C);

    // ---- top-64 per query ----
    k_topk<<<NQ, 256>>>(e1, s32, fm, out_pe, out_oi);

    // ---- updated node score + repr update 1 ----
    k_zero_score<<<NB50K, 256>>>(out_score);
    k_scatter_score_flag<<<(NQ * ME + 255) / 256, 256>>>(out_score);
    k_scale_repr<<<(N_NODES * (D / 4) + 255) / 256, 256>>>(0, NR);
    k_edge_agg<<<NQ * ME / 8, 256>>>(0, NR, NQ * ME);

    // ---- pass 2 tables ----
    k_gemm128<<<dim3(GRN, 4), 256>>>(nullptr, BUF_NR1, N_NODES, nullptr, 0, 0, nullptr, 0, nullptr, BUF_T1, BUF_T2);
    k_gemm128<<<dim3(GRE, 4), 256>>>(rel0, 0, E0C, nullptr, 256, 0, nullptr, 0, nullptr, BUF_R1, BUF_R2);

    // ---- pass 2 scores + softmax ----
    k_seg_init<<<NB50K, 256>>>();
    k_edge_score<<<E0C / 8, 256>>>(0, BUF_NR1, nullptr, rel0, E0C);
    k_seg_max<<<128, 256>>>(0, E0C);
    k_seg_exp<<<128, 256>>>(0, E0C);
    k_seg_div<<<128, 256>>>(0, nullptr, E0C);

    // ---- repr update 2 ----
    k_set_flag0<<<128, 256>>>();
    k_scale_repr<<<(N_NODES * (D / 4) + 255) / 256, 256>>>(1, nullptr);
    k_edge_agg<<<E0C / 8, 256>>>(1, nullptr, E0C);

    // ---- final linear layer + leaky relu ----
    k_gemm128<<<dim3(GRN, 2), 256>>>(nullptr, BUF_NR2, N_NODES, Wl, -1, D, bl, 1, out_repr, 0, 0);
}

// round 8
// speedup vs baseline: 1.1768x; 1.1390x over previous
#include <cuda_runtime.h>
#include <math.h>

#define N_NODES 50000
#define D 256
#define D4 1024
#define NQ 128
#define PG 256
#define E1C 32768
#define E0C 32768
#define ME 64
#define SPAD 132

// ---------------- scratch (static device globals; referenced ONLY from device code) ----------------
__device__ __align__(16) float g_M[D4 * D4];   // Wq^T Wk
__device__ __align__(16) float g_v[NQ * D];
__device__ __align__(16) float g_wz[NQ * D];
__device__ __align__(16) float g_u[NQ * D];
__device__ float g_c[NQ];
__device__ __align__(16) float g_T1[N_NODES * D];
__device__ __align__(16) float g_T2[N_NODES * D];
__device__ __align__(16) float g_R1[E1C * D];
__device__ __align__(16) float g_R2[E1C * D];
__device__ float g_logits[E1C];
__device__ float g_exp[E1C];
__device__ float g_soft[E1C];
__device__ float g_target[E1C];
__device__ unsigned g_segmax[N_NODES];
__device__ float g_segsum[N_NODES];
__device__ int g_flag[N_NODES];
__device__ __align__(16) float g_NR1[N_NODES * D];
__device__ __align__(16) float g_NR2[N_NODES * D];
__device__ int g_s1[E1C], g_d1[E1C], g_q1[E1C];
__device__ int g_s0[E0C], g_d0[E0C], g_q0[E0C];
__device__ int g_psrc[NQ * ME], g_pdst[NQ * ME];
__device__ float g_psoft[NQ * ME], g_ptgt[NQ * ME];

#define BUF_T1 1
#define BUF_T2 2
#define BUF_R1 3
#define BUF_R2 4
#define BUF_NR1 5
#define BUF_NR2 6

__device__ __forceinline__ float* dbuf(int id) {
    switch (id) {
        case BUF_T1: return g_T1;
        case BUF_T2: return g_T2;
        case BUF_R1: return g_R1;
        case BUF_R2: return g_R2;
        case BUF_NR1: return g_NR1;
        default: return g_NR2;
    }
}

__device__ __forceinline__ unsigned fenc(float f) {
    unsigned u = __float_as_uint(f);
    return (u & 0x80000000u) ? ~u : (u | 0x80000000u);
}
__device__ __forceinline__ float fdec(unsigned e) {
    return __uint_as_float((e & 0x80000000u) ? (e ^ 0x80000000u) : ~e);
}

__device__ __forceinline__ unsigned f2tf32(float x) {
    unsigned r;
    asm("cvt.rna.tf32.f32 %0, %1;" : "=r"(r) : "f"(x));
    return r;
}

__device__ __forceinline__ void mma_tf32(float* c, unsigned a0, unsigned a1, unsigned a2,
                                         unsigned a3, unsigned b0, unsigned b1) {
    asm volatile(
        "mma.sync.aligned.m16n8k8.row.col.f32.tf32.tf32.f32 "
        "{%0,%1,%2,%3}, {%4,%5,%6,%7}, {%8,%9}, {%0,%1,%2,%3};"
        : "+f"(c[0]), "+f"(c[1]), "+f"(c[2]), "+f"(c[3])
        : "r"(a0), "r"(a1), "r"(a2), "r"(a3), "r"(b0), "r"(b1));
}

// ---------------- tensor-core split-tf32 GEMM ----------------
// C[R x N] = act( X[R x 256] @ W[N x 256]^T + bias ), fp32-accurate via hi/lo tf32 split.
// 128x128 block tile, 8 warps (2 m-rows x 4 n-cols of 64x32 warp tiles).
// Output cols [0,256)->c1id, [256,512)->c2id (ldc=256); c1id==0&&c2id==0 -> external c1ext.
__global__ __launch_bounds__(256) void k_gemm128t(
    const float* __restrict__ xext, int xid, int R,
    const float* __restrict__ wext, long woff, int ldwext,
    const float* __restrict__ bias, int act,
    float* __restrict__ c1ext, int c1id, int c2id)
{
    const float* X = xid ? dbuf(xid) : xext;
    const float* W = (woff >= 0) ? (g_M + woff) : wext;
    const int ldw = (woff >= 0) ? D4 : ldwext;

    __shared__ unsigned Xh[16][SPAD], Xl[16][SPAD];
    __shared__ unsigned Wh[16][SPAD], Wl_[16][SPAD];

    const int r0 = blockIdx.x * 128;
    const int j0 = blockIdx.y * 128;
    float* Cbase;
    if (c1id == 0 && c2id == 0) Cbase = c1ext + j0;
    else Cbase = (j0 < 256) ? (dbuf(c1id) + j0) : (dbuf(c2id) + (j0 - 256));

    const int tid = threadIdx.x;
    const int wid = tid >> 5;
    const int lane = tid & 31;
    const int m0 = (wid >> 2) * 64;     // warp m offset in tile
    const int n0 = (wid & 3) * 32;      // warp n offset in tile
    const int g = lane >> 2;            // group id 0..7
    const int t4 = lane & 3;            // thread in group 0..3

    float c[4][4][4];
#pragma unroll
    for (int mi = 0; mi < 4; mi++)
#pragma unroll
        for (int nj = 0; nj < 4; nj++)
#pragma unroll
            for (int k = 0; k < 4; k++) c[mi][nj][k] = 0.f;

    float4 xv[2], wv[2];

    // prime k-block 0
#pragma unroll
    for (int i = 0; i < 2; i++) {
        int f = tid + i * 256;
        int row = f >> 2, kq = (f & 3) << 2;
        float4 v = make_float4(0.f, 0.f, 0.f, 0.f);
        if (r0 + row < R) v = *(const float4*)(X + (size_t)(r0 + row) * D + kq);
        float4 w = *(const float4*)(W + (size_t)(j0 + row) * ldw + kq);
        float vx[4] = {v.x, v.y, v.z, v.w};
        float wx[4] = {w.x, w.y, w.z, w.w};
#pragma unroll
        for (int e = 0; e < 4; e++) {
            unsigned h = f2tf32(vx[e]);
            Xh[kq + e][row] = h;
            Xl[kq + e][row] = f2tf32(vx[e] - __uint_as_float(h));
            unsigned hw = f2tf32(wx[e]);
            Wh[kq + e][row] = hw;
            Wl_[kq + e][row] = f2tf32(wx[e] - __uint_as_float(hw));
        }
    }
    __syncthreads();

    for (int kb = 0; kb < 16; kb++) {
        if (kb < 15) {
            int k0 = (kb + 1) * 16;
#pragma unroll
            for (int i = 0; i < 2; i++) {
                int f = tid + i * 256;
                int row = f >> 2, kq = (f & 3) << 2;
                xv[i] = make_float4(0.f, 0.f, 0.f, 0.f);
                if (r0 + row < R) xv[i] = *(const float4*)(X + (size_t)(r0 + row) * D + k0 + kq);
                wv[i] = *(const float4*)(W + (size_t)(j0 + row) * ldw + k0 + kq);
            }
        }
#pragma unroll
        for (int ks = 0; ks < 16; ks += 8) {
            unsigned ah[4][4], al[4][4], bh[4][2], bl[4][2];
#pragma unroll
            for (int mi = 0; mi < 4; mi++) {
                int mr = m0 + mi * 16;
                ah[mi][0] = Xh[ks + t4][mr + g];
                ah[mi][1] = Xh[ks + t4][mr + 8 + g];
                ah[mi][2] = Xh[ks + 4 + t4][mr + g];
                ah[mi][3] = Xh[ks + 4 + t4][mr + 8 + g];
                al[mi][0] = Xl[ks + t4][mr + g];
                al[mi][1] = Xl[ks + t4][mr + 8 + g];
                al[mi][2] = Xl[ks + 4 + t4][mr + g];
                al[mi][3] = Xl[ks + 4 + t4][mr + 8 + g];
            }
#pragma unroll
            for (int nj = 0; nj < 4; nj++) {
                int nc = n0 + nj * 8 + g;
                bh[nj][0] = Wh[ks + t4][nc];
                bh[nj][1] = Wh[ks + 4 + t4][nc];
                bl[nj][0] = Wl_[ks + t4][nc];
                bl[nj][1] = Wl_[ks + 4 + t4][nc];
            }
#pragma unroll
            for (int mi = 0; mi < 4; mi++)
#pragma unroll
                for (int nj = 0; nj < 4; nj++) {
                    mma_tf32(c[mi][nj], al[mi][0], al[mi][1], al[mi][2], al[mi][3],
                             bh[nj][0], bh[nj][1]);
                    mma_tf32(c[mi][nj], ah[mi][0], ah[mi][1], ah[mi][2], ah[mi][3],
                             bl[nj][0], bl[nj][1]);
                    mma_tf32(c[mi][nj], ah[mi][0], ah[mi][1], ah[mi][2], ah[mi][3],
                             bh[nj][0], bh[nj][1]);
                }
        }
        __syncthreads();
        if (kb < 15) {
#pragma unroll
            for (int i = 0; i < 2; i++) {
                int f = tid + i * 256;
                int row = f >> 2, kq = (f & 3) << 2;
                float vx[4] = {xv[i].x, xv[i].y, xv[i].z, xv[i].w};
                float wx[4] = {wv[i].x, wv[i].y, wv[i].z, wv[i].w};
#pragma unroll
                for (int e = 0; e < 4; e++) {
                    unsigned h = f2tf32(vx[e]);
                    Xh[kq + e][row] = h;
                    Xl[kq + e][row] = f2tf32(vx[e] - __uint_as_float(h));
                    unsigned hw = f2tf32(wx[e]);
                    Wh[kq + e][row] = hw;
                    Wl_[kq + e][row] = f2tf32(wx[e] - __uint_as_float(hw));
                }
            }
            __syncthreads();
        }
    }

    // epilogue: c frag (mi,nj): rows m0+mi*16+g (+8), cols n0+nj*8+t4*2 (+1)
#pragma unroll
    for (int mi = 0; mi < 4; mi++) {
#pragma unroll
        for (int half = 0; half < 2; half++) {
            int row = r0 + m0 + mi * 16 + half * 8 + g;
            if (row < R) {
#pragma unroll
                for (int nj = 0; nj < 4; nj++) {
                    int col = n0 + nj * 8 + t4 * 2;
                    float v0 = c[mi][nj][half * 2 + 0];
                    float v1 = c[mi][nj][half * 2 + 1];
                    if (bias) { v0 += bias[j0 + col]; v1 += bias[j0 + col + 1]; }
                    if (act) {
                        v0 = v0 > 0.f ? v0 : 0.01f * v0;
                        v1 = v1 > 0.f ? v1 : 0.01f * v1;
                    }
                    float2 p = make_float2(v0, v1);
                    *(float2*)(Cbase + (size_t)row * D + col) = p;
                }
            }
        }
    }
}

// g_M = A^T * B (A, B 1024x1024 row-major), fp32 SIMT (small share of total)
__global__ __launch_bounds__(256) void k_gemm128_tn(const float* __restrict__ A,
                                                    const float* __restrict__ B) {
    __shared__ float As[2][16][SPAD];
    __shared__ float Bs[2][16][SPAD];

    const int i0 = blockIdx.x * 128;
    const int j0 = blockIdx.y * 128;
    const int tid = threadIdx.x;
    const int tx = tid & 15, ty = tid >> 4;

    float acc[8][8];
#pragma unroll
    for (int r = 0; r < 8; r++)
#pragma unroll
        for (int c = 0; c < 8; c++) acc[r][c] = 0.f;

    float4 xs[2], ws[2];

#pragma unroll
    for (int i = 0; i < 2; i++) {
        int f = tid + i * 256;
        int i4 = (f & 31) << 2, kk = f >> 5;
        *(float4*)&As[0][kk][i4] = *(const float4*)(A + (size_t)kk * D4 + i0 + i4);
        *(float4*)&Bs[0][kk][i4] = *(const float4*)(B + (size_t)kk * D4 + j0 + i4);
    }
    __syncthreads();

    for (int kb = 0; kb < 64; kb++) {
        int cur = kb & 1, nxt = cur ^ 1;
        if (kb < 63) {
            int k0 = (kb + 1) * 16;
#pragma unroll
            for (int i = 0; i < 2; i++) {
                int f = tid + i * 256;
                int i4 = (f & 31) << 2, kk = f >> 5;
                xs[i] = *(const float4*)(A + (size_t)(k0 + kk) * D4 + i0 + i4);
                ws[i] = *(const float4*)(B + (size_t)(k0 + kk) * D4 + j0 + i4);
            }
        }
#pragma unroll
        for (int kk = 0; kk < 16; kk++) {
            float a[8], b[8];
            *(float4*)&a[0] = *(const float4*)&As[cur][kk][ty * 8];
            *(float4*)&a[4] = *(const float4*)&As[cur][kk][ty * 8 + 4];
            *(float4*)&b[0] = *(const float4*)&Bs[cur][kk][tx * 8];
            *(float4*)&b[4] = *(const float4*)&Bs[cur][kk][tx * 8 + 4];
#pragma unroll
            for (int r = 0; r < 8; r++)
#pragma unroll
                for (int c = 0; c < 8; c++) acc[r][c] += a[r] * b[c];
        }
        if (kb < 63) {
#pragma unroll
            for (int i = 0; i < 2; i++) {
                int f = tid + i * 256;
                int i4 = (f & 31) << 2, kk = f >> 5;
                *(float4*)&As[nxt][kk][i4] = xs[i];
                *(float4*)&Bs[nxt][kk][i4] = ws[i];
            }
            __syncthreads();
        }
    }

#pragma unroll
    for (int r = 0; r < 8; r++) {
        float* crow = g_M + (size_t)(i0 + ty * 8 + r) * D4 + j0 + tx * 8;
        *(float4*)crow = *(float4*)&acc[r][0];
        *(float4*)(crow + 4) = *(float4*)&acc[r][4];
    }
}

// edges are int32 rows of stride s32 (8 for int32 data, 16 for int64-as-int32; field f at f*fm)
__global__ void k_extract(const int* __restrict__ e1, const int* __restrict__ e0,
                          int s32, int fm) {
    int i = blockIdx.x * blockDim.x + threadIdx.x;
    if (i < E1C) {
        int q = e1[(size_t)i * s32 + 0 * fm];
        int s = e1[(size_t)i * s32 + 6 * fm];
        int d = e1[(size_t)i * s32 + 7 * fm];
        g_q1[i] = ((unsigned)q < NQ) ? q : 0;
        g_s1[i] = ((unsigned)s < N_NODES) ? s : 0;
        g_d1[i] = ((unsigned)d < N_NODES) ? d : 0;
    }
    if (i < E0C) {
        int q = e0[(size_t)i * s32 + 0 * fm];
        int s = e0[(size_t)i * s32 + 6 * fm];
        int d = e0[(size_t)i * s32 + 7 * fm];
        g_q0[i] = ((unsigned)q < NQ) ? q : 0;
        g_s0[i] = ((unsigned)s < N_NODES) ? s : 0;
        g_d0[i] = ((unsigned)d < N_NODES) ? d : 0;
    }
}

// per-query vectors from blocks of M = Wq^T Wk
__global__ void k_queryvec(const float* __restrict__ qst, const float* __restrict__ qr) {
    int q = blockIdx.x;
    int j = threadIdx.x;
    __shared__ float ss[256], tt[256], red[256];
    ss[j] = qst[q * D + j];
    tt[j] = qr[q * D + j];
    __syncthreads();
    int which = blockIdx.y;
    if (which == 0) {
        const float* row = g_M + (size_t)j * D4;
        float a = 0.f;
        for (int k = 0; k < D; k++) a += row[512 + k] * ss[k] + row[768 + k] * tt[k];
        g_v[q * D + j] = a;
    } else if (which == 1) {
        const float* row = g_M + (size_t)(256 + j) * D4;
        float a = 0.f;
        for (int k = 0; k < D; k++) a += row[512 + k] * ss[k] + row[768 + k] * tt[k];
        for (int k = 0; k < D; k++)
            a += g_M[(size_t)(512 + k) * D4 + 256 + j] * ss[k]
               + g_M[(size_t)(768 + k) * D4 + 256 + j] * tt[k];
        g_wz[q * D + j] = a;
    } else if (which == 2) {
        float a = 0.f;
        for (int k = 0; k < D; k++)
            a += g_M[(size_t)(512 + k) * D4 + j] * ss[k]
               + g_M[(size_t)(768 + k) * D4 + j] * tt[k];
        g_u[q * D + j] = a;
    } else {
        const float* rs = g_M + (size_t)(512 + j) * D4;
        const float* rt = g_M + (size_t)(768 + j) * D4;
        float ps = 0.f, pt = 0.f;
        for (int k = 0; k < D; k++) {
            ps += rs[512 + k] * ss[k] + rs[768 + k] * tt[k];
            pt += rt[512 + k] * ss[k] + rt[768 + k] * tt[k];
        }
        red[j] = ss[j] * ps + tt[j] * pt;
        __syncthreads();
        for (int s = 128; s; s >>= 1) {
            if (j < s) red[j] += red[j + s];
            __syncthreads();
        }
        if (j == 0) g_c[q] = red[0];
    }
}

// one warp per edge
__global__ void k_edge_score(int pass, int nrid, const float* __restrict__ nrext,
                             const float* __restrict__ rel, int ne) {
    int e = blockIdx.x * 8 + (threadIdx.x >> 5);
    if (e >= ne) return;
    int lane = threadIdx.x & 31;
    const int* qs = pass ? g_q1 : g_q0;
    const int* ssrc = pass ? g_s1 : g_s0;
    const int* sdst = pass ? g_d1 : g_d0;
    const float* NR = nrid ? dbuf(nrid) : nrext;
    int q = qs[e], s = ssrc[e], d = sdst[e];
    const float* ns = NR + (size_t)s * D;
    const float* nd = NR + (size_t)d * D;
    const float* re = rel + (size_t)e * D;
    const float* t1 = g_T1 + (size_t)d * D;
    const float* t2 = g_T2 + (size_t)d * D;
    const float* r1 = g_R1 + (size_t)e * D;
    const float* r2 = g_R2 + (size_t)e * D;
    const float* vq = g_v + q * D;
    const float* wq = g_wz + q * D;
    const float* uq = g_u + q * D;
    float a = 0.f;
#pragma unroll
    for (int i = 0; i < 8; i++) {
        int k = lane + 32 * i;
        a += ns[k] * (t1[k] + r1[k] + vq[k]);
        a += re[k] * (t2[k] + r2[k] + wq[k]);
        a += uq[k] * nd[k];
    }
#pragma unroll
    for (int o = 16; o; o >>= 1) a += __shfl_xor_sync(0xffffffffu, a, o);
    if (lane == 0) g_logits[e] = a + g_c[q];
}

__global__ void k_seg_init() {
    int i = blockIdx.x * blockDim.x + threadIdx.x;
    if (i < N_NODES) {
        g_segmax[i] = 0u;
        g_segsum[i] = 0.f;
        g_flag[i] = 0;
    }
}

__global__ void k_seg_max(int pass, int ne) {
    int i = blockIdx.x * blockDim.x + threadIdx.x;
    if (i < ne) {
        const int* seg = pass ? g_s1 : g_s0;
        atomicMax(&g_segmax[seg[i]], fenc(g_logits[i]));
    }
}

__global__ void k_seg_exp(int pass, int ne) {
    int i = blockIdx.x * blockDim.x + threadIdx.x;
    if (i < ne) {
        const int* seg = pass ? g_s1 : g_s0;
        float m = fdec(g_segmax[seg[i]]);
        float e = expf(g_logits[i] - m);
        g_exp[i] = e;
        atomicAdd(&g_segsum[seg[i]], e);
    }
}

__global__ void k_seg_div(int pass, const float* __restrict__ vscore, int ne) {
    int i = blockIdx.x * blockDim.x + threadIdx.x;
    if (i < ne) {
        const int* seg = pass ? g_s1 : g_s0;
        float sft = g_exp[i] / g_segsum[seg[i]];
        g_soft[i] = sft;
        if (vscore) g_target[i] = sft * vscore[seg[i]];
    }
}

// per-query bitonic sort of 256 (target, idx), descending value, ties by ascending idx
__global__ void k_topk(const int* __restrict__ edges1, int s32, int fm,
                       float* __restrict__ out_pe, float* __restrict__ out_oi) {
    int q = blockIdx.x;
    int t = threadIdx.x;
    __shared__ float sv[256];
    __shared__ int si[256];
    sv[t] = g_target[q * PG + t];
    si[t] = t;
    __syncthreads();
    for (int k = 2; k <= 256; k <<= 1) {
        for (int j = k >> 1; j > 0; j >>= 1) {
            int ixj = t ^ j;
            if (ixj > t) {
                float va = sv[t], vb = sv[ixj];
                int ia = si[t], ib = si[ixj];
                bool before = (va > vb) || (va == vb && ia < ib);
                bool up = ((t & k) == 0);
                if (up ? !before : before) {
                    sv[t] = vb; sv[ixj] = va;
                    si[t] = ib; si[ixj] = ia;
                }
            }
            __syncthreads();
        }
    }
    if (t < ME) {
        int oi = q * PG + si[t];
        int po = q * ME + t;
        out_oi[po] = (float)oi;
#pragma unroll
        for (int f = 0; f < 8; f++)
            out_pe[(size_t)po * 8 + f] = (float)edges1[(size_t)oi * s32 + f * fm];
        int s = edges1[(size_t)oi * s32 + 6 * fm];
        int d = edges1[(size_t)oi * s32 + 7 * fm];
        g_psrc[po] = ((unsigned)s < N_NODES) ? s : 0;
        g_pdst[po] = ((unsigned)d < N_NODES) ? d : 0;
        g_psoft[po] = g_soft[oi];
        g_ptgt[po] = sv[t];
    }
}

__global__ void k_zero_score(float* __restrict__ out_score) {
    int i = blockIdx.x * blockDim.x + threadIdx.x;
    if (i < N_NODES) out_score[i] = 0.f;
}

__global__ void k_scatter_score_flag(float* __restrict__ out_score) {
    int i = blockIdx.x * blockDim.x + threadIdx.x;
    if (i < NQ * ME) {
        atomicAdd(&out_score[g_pdst[i]], g_ptgt[i]);
        g_flag[g_psrc[i]] = 1;
    }
}

__global__ void k_set_flag0() {
    int i = blockIdx.x * blockDim.x + threadIdx.x;
    if (i < E0C) g_flag[g_s0[i]] = 1;
}

// mode 0: out = g_NR1, in = external NR ; mode 1: out = g_NR2, in = g_NR1
__global__ void k_scale_repr(int mode, const float* __restrict__ nrext) {
    size_t i = (size_t)blockIdx.x * blockDim.x + threadIdx.x;
    if (i < (size_t)N_NODES * (D / 4)) {
        const float4* in = mode ? (const float4*)g_NR1 : (const float4*)nrext;
        float4* out = mode ? (float4*)g_NR2 : (float4*)g_NR1;
        int n = (int)(i >> 6);
        float sc = g_flag[n] ? 0.2f : 1.0f;
        float4 vv = in[i];
        vv.x *= sc; vv.y *= sc; vv.z *= sc; vv.w *= sc;
        out[i] = vv;
    }
}

// mode 0: pruned edges, base external NR, acc g_NR1 ; mode 1: edges0, base g_NR1, acc g_NR2
__global__ void k_edge_agg(int mode, const float* __restrict__ nrext, int ne) {
    int e = blockIdx.x * 8 + (threadIdx.x >> 5);
    if (e >= ne) return;
    int lane = threadIdx.x & 31;
    const int* src = mode ? g_s0 : g_psrc;
    const int* dst = mode ? g_d0 : g_pdst;
    const float* w = mode ? g_soft : g_psoft;
    const float* base = mode ? g_NR1 : nrext;
    float* acc = mode ? g_NR2 : g_NR1;
    float cf = 0.8f * w[e];
    const float* bd = base + (size_t)dst[e] * D;
    float* as = acc + (size_t)src[e] * D;
#pragma unroll
    for (int i = 0; i < 8; i++) atomicAdd(as + lane + 32 * i, cf * bd[lane + 32 * i]);
}

// ---------------- host: kernel launches ONLY ----------------
extern "C" void kernel_launch(void* const* d_in, const int* in_sizes, int n_in,
                              void* d_out, int out_size) {
    int iVS = -1, iNR = -1, iE0 = -1, iE1 = -1, iR0 = -1, iR1 = -1;
    int iQA = -1, iQB = -1, iWA = -1, iWB = -1, iWL = -1, iBL = -1;
    for (int i = 0; i < n_in; i++) {
        long sz = in_sizes[i];
        if (sz == 50000) iVS = i;
        else if (sz == 12800000) iNR = i;
        else if (sz == 262144 || sz == 524288) { if (iE0 < 0) iE0 = i; else iE1 = i; }
        else if (sz == 8388608) { if (iR0 < 0) iR0 = i; else iR1 = i; }
        else if (sz == 32768) { if (iQA < 0) iQA = i; else iQB = i; }
        else if (sz == 1048576) { if (iWA < 0) iWA = i; else iWB = i; }
        else if (sz == 65536) iWL = i;
        else if (sz == 256) iBL = i;
    }
    bool dictOrder = (in_sizes[0] == 50000);

    const float* vscore = (const float*)d_in[iVS];
    const float* NR = (const float*)d_in[iNR];
    const int* e0 = (const int*)d_in[iE0];
    const int* e1 = (const int*)d_in[iE1];
    const float* rel0 = (const float*)d_in[iR0];
    const float* rel1 = (const float*)d_in[iR1];
    const float* qst = (const float*)d_in[dictOrder ? iQA : iQB];
    const float* qr = (const float*)d_in[dictOrder ? iQB : iQA];
    const float* Wq = (const float*)d_in[dictOrder ? iWA : iWB];
    const float* Wk = (const float*)d_in[dictOrder ? iWB : iWA];
    const float* Wl = (const float*)d_in[iWL];
    const float* bl = (const float*)d_in[iBL];

    int s32 = in_sizes[iE0] / 32768;
    int fm = s32 >> 3;

    float* out = (float*)d_out;
    float* out_score = out;
    float* out_repr = out + N_NODES;
    float* out_pe = out_repr + (size_t)N_NODES * D;
    float* out_oi = out_pe + (size_t)NQ * ME * 8;

    const int NB50K = (N_NODES + 255) / 256;
    const int GRN = (N_NODES + 127) / 128;   // 391
    const int GRE = E1C / 128;               // 256

    k_extract<<<128, 256>>>(e1, e0, s32, fm);
    k_gemm128_tn<<<dim3(8, 8), 256>>>(Wq, Wk);
    k_queryvec<<<dim3(NQ, 4), 256>>>(qst, qr);

    // ---- pass 1 tables: T1||T2 and R1||R2 fused (N=512 each), tensor-core split-tf32 ----
    k_gemm128t<<<dim3(GRN, 4), 256>>>(NR, 0, N_NODES, nullptr, 0, 0, nullptr, 0, nullptr, BUF_T1, BUF_T2);
    k_gemm128t<<<dim3(GRE, 4), 256>>>(rel1, 0, E1C, nullptr, 256, 0, nullptr, 0, nullptr, BUF_R1, BUF_R2);

    // ---- pass 1 scores + segment softmax ----
    k_seg_init<<<NB50K, 256>>>();
    k_edge_score<<<E1C / 8, 256>>>(1, 0, NR, rel1, E1C);
    k_seg_max<<<128, 256>>>(1, E1C);
    k_seg_exp<<<128, 256>>>(1, E1C);
    k_seg_div<<<128, 256>>>(1, vscore, E1C);

    // ---- top-64 per query ----
    k_topk<<<NQ, 256>>>(e1, s32, fm, out_pe, out_oi);

    // ---- updated node score + repr update 1 ----
    k_zero_score<<<NB50K, 256>>>(out_score);
    k_scatter_score_flag<<<(NQ * ME + 255) / 256, 256>>>(out_score);
    k_scale_repr<<<(N_NODES * (D / 4) + 255) / 256, 256>>>(0, NR);
    k_edge_agg<<<NQ * ME / 8, 256>>>(0, NR, NQ * ME);

    // ---- pass 2 tables ----
    k_gemm128t<<<dim3(GRN, 4), 256>>>(nullptr, BUF_NR1, N_NODES, nullptr, 0, 0, nullptr, 0, nullptr, BUF_T1, BUF_T2);
    k_gemm128t<<<dim3(GRE, 4), 256>>>(rel0, 0, E0C, nullptr, 256, 0, nullptr, 0, nullptr, BUF_R1, BUF_R2);

    // ---- pass 2 scores + softmax ----
    k_seg_init<<<NB50K, 256>>>();
    k_edge_score<<<E0C / 8, 256>>>(0, BUF_NR1, nullptr, rel0, E0C);
    k_seg_max<<<128, 256>>>(0, E0C);
    k_seg_exp<<<128, 256>>>(0, E0C);
    k_seg_div<<<128, 256>>>(0, nullptr, E0C);

    // ---- repr update 2 ----
    k_set_flag0<<<128, 256>>>();
    k_scale_repr<<<(N_NODES * (D / 4) + 255) / 256, 256>>>(1, nullptr);
    k_edge_agg<<<E0C / 8, 256>>>(1, nullptr, E0C);

    // ---- final linear layer + leaky relu (N=256 external out) ----
    k_gemm128t<<<dim3(GRN, 2), 256>>>(nullptr, BUF_NR2, N_NODES, Wl, -1, D, bl, 1, out_repr, 0, 0);
}